// round 4
// baseline (speedup 1.0000x reference)
#include <cuda_runtime.h>
#include <cstdint>
#include <math.h>

#define NUMB   4
#define PRE    1024
#define CHUNK  2048
#define MAXN   200000
#define MAXCH  ((MAXN + CHUNK - 1) / CHUNK)   /* 98 */
#define MROUNDS 7

// ---------------- device scratch (static, no runtime alloc) ----------------
__device__ unsigned long long g_keys[NUMB][MAXN];
__device__ int                g_cnt[NUMB];
__device__ unsigned long long g_lists[2][NUMB][MAXCH * CHUNK];
__device__ unsigned long long g_prec[NUMB][CHUNK];
__device__ unsigned long long g_sel[NUMB][PRE];
__device__ float              g_boxes[NUMB][PRE][8];
__device__ unsigned           g_mask[NUMB][PRE][32];
__device__ unsigned           g_rowflag[NUMB][32];

__device__ __forceinline__ float exp_cr(float x)  { return (float)exp((double)x); }
__device__ __forceinline__ float atan2_cr(float y, float x) {
    return (float)atan2((double)y, (double)x);
}

// ---------------- K0: zero counters / flags ----------------
__global__ void k_zero_misc() {
    int t = threadIdx.x;
    if (t < NUMB) g_cnt[t] = 0;
    if (t < NUMB * 32) ((unsigned*)g_rowflag)[t] = 0;
}

__global__ void k_zero_out(float* out, int n) {
    int i = blockIdx.x * blockDim.x + threadIdx.x;
    if (i < n) out[i] = 0.0f;
}

// ---------------- K1: APPROX score pass (ordering within ~1e-6 is enough) -
// warp-per-point: lane k covers feature rows [k*8, k*8+8)
__global__ void __launch_bounds__(256) k_score(
        const float* __restrict__ feat,
        const int*   __restrict__ bidx,
        const float* __restrict__ Wc,
        const float* __restrict__ Wr,
        int N) {
    const int warp = threadIdx.x >> 5;
    const int lane = threadIdx.x & 31;

    float wd[8], w8[8];
#pragma unroll
    for (int c = 0; c < 8; c++) {
        int row = lane * 8 + c;
        wd[c] = Wc[row * 2 + 1] - Wc[row * 2 + 0];
        w8[c] = Wr[row * 9 + 8];
    }

    __shared__ unsigned long long skeys[256];
    __shared__ int sbatch[256];
    __shared__ int hist[NUMB];
    __shared__ int base[NUMB];
    if (threadIdx.x < NUMB) hist[threadIdx.x] = 0;

    const int tile0 = blockIdx.x * 256;

    for (int i = 0; i < 32; i++) {
        int p = tile0 + warp * 32 + i;
        float accd = 0.0f, accr = 0.0f;
        if (p < N) {
            const float4* f4 = (const float4*)(feat + (size_t)p * 256);
            float4 a = f4[lane * 2 + 0];
            float4 b = f4[lane * 2 + 1];
            accd = a.x * wd[0] + a.y * wd[1] + a.z * wd[2] + a.w * wd[3]
                 + b.x * wd[4] + b.y * wd[5] + b.z * wd[6] + b.w * wd[7];
            accr = a.x * w8[0] + a.y * w8[1] + a.z * w8[2] + a.w * w8[3]
                 + b.x * w8[4] + b.y * w8[5] + b.z * w8[6] + b.w * w8[7];
        }
#pragma unroll
        for (int o = 16; o > 0; o >>= 1) {
            accd += __shfl_xor_sync(0xffffffffu, accd, o);
            accr += __shfl_xor_sync(0xffffffffu, accr, o);
        }
        if (lane == 0) {
            int slot = warp * 32 + i;
            if (p < N) {
                // sigmoid(d)*sigmoid(r) == softmax[1]*sigmoid — approx only
                float s = 1.0f / ((1.0f + expf(-accd)) * (1.0f + expf(-accr)));
                skeys[slot] = ((unsigned long long)__float_as_uint(s) << 32) |
                              (unsigned)(~(unsigned)p);
                sbatch[slot] = bidx[p];
            } else {
                sbatch[slot] = -1;
            }
        }
    }
    __syncthreads();

    int b = sbatch[threadIdx.x];
    int rank = -1;
    if (b >= 0) rank = atomicAdd(&hist[b], 1);
    __syncthreads();
    if (threadIdx.x < NUMB) {
        int h = hist[threadIdx.x];
        base[threadIdx.x] = h ? atomicAdd(&g_cnt[threadIdx.x], h) : 0;
    }
    __syncthreads();
    if (b >= 0) {
        int pos = base[b] + rank;
        if (pos < MAXN) g_keys[b][pos] = skeys[threadIdx.x];
    }
}

// ---------------- K2: leaf bitonic sort (full 2048, descending) -----------
__global__ void k_leaf() {
    int b = blockIdx.y;
    int c = blockIdx.x;
    int cnt = g_cnt[b];
    int nlists = (cnt + CHUNK - 1) / CHUNK;
    if (nlists < 1) nlists = 1;
    if (c >= nlists) return;

    __shared__ unsigned long long s[CHUNK];
    int gbase = c * CHUNK;
#pragma unroll
    for (int rr = 0; rr < 2; rr++) {
        int i = threadIdx.x + rr * 1024;
        int g = gbase + i;
        s[i] = (g < cnt) ? g_keys[b][g] : 0ull;
    }

    for (unsigned k = 2; k <= CHUNK; k <<= 1) {
        for (unsigned j = k >> 1; j > 0; j >>= 1) {
            __syncthreads();
#pragma unroll
            for (int rr = 0; rr < 2; rr++) {
                unsigned t = threadIdx.x + rr * 1024;
                unsigned ixj = t ^ j;
                if (ixj > t) {
                    unsigned long long a = s[t], bb = s[ixj];
                    bool desc = ((t & k) == 0);
                    if (desc ? (a < bb) : (a > bb)) { s[t] = bb; s[ixj] = a; }
                }
            }
        }
    }
    __syncthreads();
    g_lists[0][b][c * CHUNK + threadIdx.x] = s[threadIdx.x];
    g_lists[0][b][c * CHUNK + threadIdx.x + 1024] = s[threadIdx.x + 1024];
}

// ---------------- K3: merge round (2 desc 2048-lists -> top 2048) ---------
__global__ void k_merge(int round) {
    int b = blockIdx.y;
    int c = blockIdx.x;
    int cnt = g_cnt[b];
    int nl0 = (cnt + CHUNK - 1) / CHUNK;
    if (nl0 < 1) nl0 = 1;
    int sh = round - 1;
    int nl_in = (nl0 + (1 << sh) - 1) >> sh;
    if (nl_in < 1) nl_in = 1;
    if (2 * c >= nl_in) return;

    int src = (round - 1) & 1;
    int dst = round & 1;
    int t = threadIdx.x;

    if (2 * c + 1 < nl_in) {
        __shared__ unsigned long long s[2 * CHUNK];
        const unsigned long long* A = &g_lists[src][b][(2 * c) * CHUNK];
        const unsigned long long* B = &g_lists[src][b][(2 * c + 1) * CHUNK];
        s[t]               = A[t];
        s[t + 1024]        = A[t + 1024];
        s[2048 + t]        = B[2047 - t];        // B reversed -> ascending
        s[3072 + t]        = B[1023 - t];
        for (unsigned j = 2048; j > 0; j >>= 1) {
            __syncthreads();
#pragma unroll
            for (int rr = 0; rr < 4; rr++) {
                unsigned tt = t + rr * 1024;
                unsigned ixj = tt ^ j;
                if (ixj > tt) {
                    unsigned long long a = s[tt], bb = s[ixj];
                    if (a < bb) { s[tt] = bb; s[ixj] = a; }
                }
            }
        }
        __syncthreads();
        g_lists[dst][b][c * CHUNK + t]        = s[t];
        g_lists[dst][b][c * CHUNK + t + 1024] = s[t + 1024];
    } else {
        g_lists[dst][b][c * CHUNK + t]        = g_lists[src][b][(2 * c) * CHUNK + t];
        g_lists[dst][b][c * CHUNK + t + 1024] = g_lists[src][b][(2 * c) * CHUNK + t + 1024];
    }
}

// ---------------- K4: PRECISE rescore of 2048 candidates per batch --------
// warp per candidate; compensated f32 (TwoProd+TwoSum) per lane, combined
// and reduced in double -> essentially the exact score, rounded to f32.
__global__ void __launch_bounds__(128) k_rescore(
        const float* __restrict__ feat,
        const float* __restrict__ Wc,
        const float* __restrict__ bc,
        const float* __restrict__ Wr,
        const float* __restrict__ br,
        int N) {
    __shared__ float swc0[256], swc1[256], sw8[256];
    for (int i = threadIdx.x; i < 256; i += 128) {
        swc0[i] = Wc[2 * i + 0];
        swc1[i] = Wc[2 * i + 1];
        sw8[i]  = Wr[9 * i + 8];
    }
    __syncthreads();

    const int b = blockIdx.y;
    const int warp = threadIdx.x >> 5;
    const int lane = threadIdx.x & 31;
    const int k = blockIdx.x * 4 + warp;

    unsigned long long key = g_lists[MROUNDS & 1][b][k];
    unsigned idx = ~(unsigned)(key & 0xffffffffu);
    bool valid = (idx < (unsigned)N);

    double d0 = 0.0, d1 = 0.0, d2 = 0.0;
    if (valid) {
        const float4* f4 = (const float4*)(feat + (size_t)idx * 256);
        float4 a  = f4[lane * 2 + 0];
        float4 c4 = f4[lane * 2 + 1];
        float fv[8] = {a.x, a.y, a.z, a.w, c4.x, c4.y, c4.z, c4.w};
        const float* wp[3] = {&swc0[lane * 8], &swc1[lane * 8], &sw8[lane * 8]};
        double* dp[3] = {&d0, &d1, &d2};
#pragma unroll
        for (int o = 0; o < 3; o++) {
            float s = 0.0f, comp = 0.0f;
#pragma unroll
            for (int c = 0; c < 8; c++) {
                float v = fv[c], w = wp[o][c];
                float p = __fmul_rn(v, w);
                float e = __fmaf_rn(v, w, -p);      // exact product tail
                float t = __fadd_rn(s, p);          // Knuth TwoSum
                float bv = __fadd_rn(t, -s);
                float c1 = __fadd_rn(s, -__fadd_rn(t, -bv));
                float c2 = __fadd_rn(p, -bv);
                comp = __fadd_rn(comp, __fadd_rn(c1, c2));
                comp = __fadd_rn(comp, e);
                s = t;
            }
            *dp[o] = (double)s + (double)comp;
        }
    }
#pragma unroll
    for (int o = 16; o > 0; o >>= 1) {
        d0 += __shfl_xor_sync(0xffffffffu, d0, o);
        d1 += __shfl_xor_sync(0xffffffffu, d1, o);
        d2 += __shfl_xor_sync(0xffffffffu, d2, o);
    }

    if (lane == 0) {
        unsigned long long outk = 0ull;
        if (valid) {
            double l0 = d0 + (double)bc[0];
            double l1 = d1 + (double)bc[1];
            double r8 = d2 + (double)br[8];
            double m  = fmax(l0, l1);
            double e0 = exp(l0 - m);
            double e1 = exp(l1 - m);
            double conf = e1 / (e0 + e1);
            double scr  = 1.0 / (1.0 + exp(-r8));
            float sf = (float)(conf * scr);
            outk = ((unsigned long long)__float_as_uint(sf) << 32) |
                   (unsigned)(key & 0xffffffffu);
        }
        g_prec[b][k] = outk;
    }
}

// ---------------- K5: re-rank 2048 precise keys -> top 1024 ---------------
__global__ void k_rank() {
    const int b = blockIdx.x;
    const int t = threadIdx.x;
    __shared__ unsigned long long s[CHUNK];
    s[t]        = g_prec[b][t];
    s[t + 1024] = g_prec[b][t + 1024];

    for (unsigned k = 2; k <= CHUNK; k <<= 1) {
        for (unsigned j = k >> 1; j > 0; j >>= 1) {
            __syncthreads();
#pragma unroll
            for (int rr = 0; rr < 2; rr++) {
                unsigned tt = t + rr * 1024;
                unsigned ixj = tt ^ j;
                if (ixj > tt) {
                    unsigned long long a = s[tt], bb = s[ixj];
                    bool desc = ((tt & k) == 0);
                    if (desc ? (a < bb) : (a > bb)) { s[tt] = bb; s[ixj] = a; }
                }
            }
        }
    }
    __syncthreads();
    g_sel[b][t] = s[t];
}

// ---------------- K6: decode boxes for selected 4096 points --------------
__global__ void __launch_bounds__(128) k_decode(
        const float* __restrict__ feat,
        const int*   __restrict__ coor,
        const float* __restrict__ Wr,
        const float* __restrict__ br,
        int N) {
    __shared__ float sW[256 * 9];
    __shared__ float srow[4][256];
    for (int i = threadIdx.x; i < 256 * 9; i += 128) sW[i] = Wr[i];
    __syncthreads();

    const int b = blockIdx.y;
    const int warp = threadIdx.x >> 5;
    const int lane = threadIdx.x & 31;
    const int k = blockIdx.x * 4 + warp;

    unsigned long long key = g_sel[b][k];
    unsigned idx = ~(unsigned)(key & 0xffffffffu);
    bool valid = (idx < (unsigned)N);
    if (!valid) idx = 0;

    {
        const float4* f4 = (const float4*)(feat + (size_t)idx * 256);
        float4 a = f4[lane * 2 + 0];
        float4 c4 = f4[lane * 2 + 1];
        ((float4*)srow[warp])[lane * 2 + 0] = a;
        ((float4*)srow[warp])[lane * 2 + 1] = c4;
    }
    __syncwarp();

    float acc = 0.0f;
    if (lane < 8) {
        const float* row = srow[warp];
#pragma unroll 8
        for (int kk = 0; kk < 256; kk++) {
            acc = __fmaf_rn(row[kk], sW[kk * 9 + lane], acc);
        }
        acc = __fadd_rn(acc, br[lane]);
    }

    float r[8];
#pragma unroll
    for (int j = 0; j < 8; j++) r[j] = __shfl_sync(0xffffffffu, acc, j);

    if (lane == 0) {
        float out[8];
        if (valid) {
            float cx = __fmul_rn((float)coor[(size_t)idx * 2 + 0], 0.8f);
            float cy = __fmul_rn((float)coor[(size_t)idx * 2 + 1], 0.8f);
            out[0] = __fadd_rn(cx, r[0]);
            out[1] = __fadd_rn(cy, r[1]);
            out[2] = r[2];
            out[3] = exp_cr(fminf(fmaxf(r[3], -6.0f), 6.0f));
            out[4] = exp_cr(fminf(fmaxf(r[4], -6.0f), 6.0f));
            out[5] = exp_cr(fminf(fmaxf(r[5], -6.0f), 6.0f));
            out[6] = atan2_cr(r[6], r[7]);
            out[7] = __uint_as_float((unsigned)(key >> 32));
        } else {
#pragma unroll
            for (int j = 0; j < 8; j++) out[j] = 0.0f;
        }
#pragma unroll
        for (int j = 0; j < 8; j++) g_boxes[b][k][j] = out[j];
    }
}

// ---------------- K7: IoU suppression bitmask (parallel) ------------------
__global__ void k_mask() {
    const int b = blockIdx.y;
    const int j = threadIdx.x;                 // column
    __shared__ float sx1[PRE], sx2[PRE], sy1[PRE], sy2[PRE], sa[PRE];

    float x = g_boxes[b][j][0], y = g_boxes[b][j][1];
    float l = g_boxes[b][j][3], w = g_boxes[b][j][4];
    bool jv = (~(unsigned)(g_sel[b][j] & 0xffffffffu)) < 0x7fffffffu;
    if (jv) {
        float lh = __fmul_rn(l, 0.5f);
        float wh = __fmul_rn(w, 0.5f);
        sx1[j] = __fadd_rn(x, -lh); sx2[j] = __fadd_rn(x, lh);
        sy1[j] = __fadd_rn(y, -wh); sy2[j] = __fadd_rn(y, wh);
        sa[j]  = __fmul_rn(l, w);
    } else {
        sx1[j] = 1e30f; sx2[j] = -1e30f;
        sy1[j] = 1e30f; sy2[j] = -1e30f;
        sa[j]  = 0.0f;
    }
    __syncthreads();

    const int i0 = blockIdx.x * 32;
    const float X1 = sx1[j], X2 = sx2[j], Y1 = sy1[j], Y2 = sy2[j], A = sa[j];
    for (int ii = 0; ii < 32; ii++) {
        int i = i0 + ii;
        float ix = fmaxf(__fadd_rn(fminf(sx2[i], X2), -fmaxf(sx1[i], X1)), 0.0f);
        float iy = fmaxf(__fadd_rn(fminf(sy2[i], Y2), -fmaxf(sy1[i], Y1)), 0.0f);
        float inter = __fmul_rn(ix, iy);
        float uni = __fadd_rn(__fadd_rn(sa[i], A), -inter);
        float iou = __fdiv_rn(inter, fmaxf(uni, 1e-6f));
        bool s = (j > i) && (iou > 0.1f);
        unsigned bal = __ballot_sync(0xffffffffu, s);
        if ((j & 31) == 0) {
            g_mask[b][i][j >> 5] = bal;
            if (bal) atomicOr(&g_rowflag[b][i >> 5], 1u << (i & 31));
        }
    }
}

// ---------------- K8: serial greedy scan (sparse rows only) + outputs -----
__global__ void k_scan_out(float* __restrict__ dout, int out_size) {
    const int b = blockIdx.x;
    const int t = threadIdx.x;
    __shared__ unsigned srem[32];

    if (t < 32) {
        unsigned rem = 0;
        unsigned flags = g_rowflag[b][t];
        for (int w = 0; w < 32; w++) {
            unsigned fw = __shfl_sync(0xffffffffu, flags, w);
            while (fw) {
                int bp = __ffs(fw) - 1;
                fw &= fw - 1;
                int i = w * 32 + bp;
                unsigned owner = __shfl_sync(0xffffffffu, rem, i >> 5);
                if (!((owner >> (i & 31)) & 1u)) {
                    rem |= g_mask[b][i][t];
                }
            }
        }
        srem[t] = rem;
    }
    __syncthreads();

    bool jv = (~(unsigned)(g_sel[b][t] & 0xffffffffu)) < 0x7fffffffu;
    bool keep = jv && !((srem[t >> 5] >> (t & 31)) & 1u);
    float kf = keep ? 1.0f : 0.0f;

    int obase = (b * PRE + t) * 8;
#pragma unroll
    for (int c = 0; c < 8; c++) {
        if (obase + c < out_size) dout[obase + c] = g_boxes[b][t][c] * kf;
    }
    int lbpos = NUMB * PRE * 8 + b * PRE + t;          // label section (always 0)
    if (lbpos < out_size) dout[lbpos] = 0.0f;
    int kppos = NUMB * PRE * 9 + b * PRE + t;          // keep section
    if (kppos < out_size) dout[kppos] = kf;
}

// ---------------- launcher ----------------
extern "C" void kernel_launch(void* const* d_in, const int* in_sizes, int n_in,
                              void* d_out, int out_size) {
    const float* feat  = (const float*)d_in[0];
    const int*   bidx  = (const int*)d_in[1];
    const int*   coor  = (const int*)d_in[2];
    const float* Wc    = (const float*)d_in[3];
    const float* bc    = (const float*)d_in[4];
    const float* Wr    = (const float*)d_in[5];
    const float* br    = (const float*)d_in[6];
    float* out = (float*)d_out;

    const int N = in_sizes[1];

    k_zero_misc<<<1, 256>>>();
    k_zero_out<<<(out_size + 255) / 256, 256>>>(out, out_size);

    k_score<<<(N + 255) / 256, 256>>>(feat, bidx, Wc, Wr, N);

    k_leaf<<<dim3(MAXCH, NUMB), 1024>>>();
    for (int r = 1; r <= MROUNDS; r++) {
        k_merge<<<dim3((MAXCH + 1) / 2, NUMB), 1024>>>(r);
    }

    k_rescore<<<dim3(CHUNK / 4, NUMB), 128>>>(feat, Wc, bc, Wr, br, N);
    k_rank<<<NUMB, 1024>>>();

    k_decode<<<dim3(PRE / 4, NUMB), 128>>>(feat, coor, Wr, br, N);
    k_mask<<<dim3(PRE / 32, NUMB), 1024>>>();
    k_scan_out<<<NUMB, 1024>>>(out, out_size);
}